// round 1
// baseline (speedup 1.0000x reference)
#include <cuda_runtime.h>

#define D_  8
#define NT_ 2048
#define N_  64
#define NH_ 8

// Scratch (device globals: allocation-free rule-compliant)
__device__ float g_QrT [D_*NH_*N_*NT_];  // [b][h][i][u]
__device__ float g_Er  [D_*NH_*NT_*N_]; // [b][h][u][i]
__device__ float g_part[D_*NH_*NT_*N_]; // [b][h][t][i]

// ---------------- K1: Qr / Er precompute ----------------
// grid (16 u_tiles, 8 b), 256 threads
#define K1_SMEM_FLOATS (64*132 + 64*68 + 64*68)
#define K1_SMEM (K1_SMEM_FLOATS * 4)

__global__ __launch_bounds__(256) void k1_kernel(const float* __restrict__ R,
                                                 const float* __restrict__ Q,
                                                 const float* __restrict__ E) {
    extern __shared__ float sm[];
    float* sR  = sm;              // [j][u] 64 x 132 (R tile transposed)
    float* sQT = sR + 64*132;     // [j][i] 64 x 68
    float* sET = sQT + 64*68;     // [j][i] 64 x 68
    const int tid = threadIdx.x;
    const int b   = blockIdx.y;
    const int u0  = blockIdx.x * 128;

    // Load R[b, u0..u0+127, :] transposed into sR[j][u]
    for (int p = tid; p < 128*16; p += 256) {
        int u = p >> 4, j4 = (p & 15) << 2;
        float4 v = *(const float4*)&R[((size_t)b*NT_ + u0 + u)*N_ + j4];
        sR[(j4+0)*132 + u] = v.x;
        sR[(j4+1)*132 + u] = v.y;
        sR[(j4+2)*132 + u] = v.z;
        sR[(j4+3)*132 + u] = v.w;
    }

    for (int h = 0; h < NH_; h++) {
        __syncthreads();  // protect sQT/sET from previous iteration's readers
        for (int p = tid; p < 64*16; p += 256) {
            int i = p >> 4, j4 = (p & 15) << 2;
            float4 q = *(const float4*)&Q[((size_t)h*N_ + i)*N_ + j4];
            float4 e = *(const float4*)&E[((size_t)h*N_ + i)*N_ + j4];
            sQT[(j4+0)*68 + i] = q.x; sQT[(j4+1)*68 + i] = q.y;
            sQT[(j4+2)*68 + i] = q.z; sQT[(j4+3)*68 + i] = q.w;
            sET[(j4+0)*68 + i] = e.x; sET[(j4+1)*68 + i] = e.y;
            sET[(j4+2)*68 + i] = e.z; sET[(j4+3)*68 + i] = e.w;
        }
        __syncthreads();
        const int bh = b*NH_ + h;

        // Phase A: QrT[i][u] = sum_j sQT[j][i] * sR[j][u]   (4i x 8u microtile)
        {
            const int ig = tid >> 4, ug = tid & 15;
            const int ib = ig * 4, ub = ug * 8;
            float c[4][8];
            #pragma unroll
            for (int a = 0; a < 4; a++)
                #pragma unroll
                for (int bb = 0; bb < 8; bb++) c[a][bb] = 0.f;
            #pragma unroll 8
            for (int j = 0; j < 64; j++) {
                float4 aq = *(const float4*)&sQT[j*68 + ib];
                float4 r0 = *(const float4*)&sR [j*132 + ub];
                float4 r1 = *(const float4*)&sR [j*132 + ub + 4];
                float av[4] = {aq.x, aq.y, aq.z, aq.w};
                float rv[8] = {r0.x, r0.y, r0.z, r0.w, r1.x, r1.y, r1.z, r1.w};
                #pragma unroll
                for (int a = 0; a < 4; a++)
                    #pragma unroll
                    for (int bb = 0; bb < 8; bb++) c[a][bb] += av[a]*rv[bb];
            }
            #pragma unroll
            for (int a = 0; a < 4; a++) {
                float* dst = &g_QrT[((size_t)bh*N_ + ib + a)*NT_ + u0 + ub];
                *(float4*)(dst)     = make_float4(c[a][0], c[a][1], c[a][2], c[a][3]);
                *(float4*)(dst + 4) = make_float4(c[a][4], c[a][5], c[a][6], c[a][7]);
            }
        }
        // Phase B: Er[u][i] = sum_j sR[j][u] * sET[j][i]   (8u x 4i microtile)
        {
            const int ug = tid >> 4, ig = tid & 15;
            const int ub = ug * 8, ib = ig * 4;
            float c[8][4];
            #pragma unroll
            for (int r = 0; r < 8; r++)
                #pragma unroll
                for (int a = 0; a < 4; a++) c[r][a] = 0.f;
            #pragma unroll 8
            for (int j = 0; j < 64; j++) {
                float4 ae = *(const float4*)&sET[j*68 + ib];
                float4 r0 = *(const float4*)&sR [j*132 + ub];
                float4 r1 = *(const float4*)&sR [j*132 + ub + 4];
                float av[4] = {ae.x, ae.y, ae.z, ae.w};
                float rv[8] = {r0.x, r0.y, r0.z, r0.w, r1.x, r1.y, r1.z, r1.w};
                #pragma unroll
                for (int r = 0; r < 8; r++)
                    #pragma unroll
                    for (int a = 0; a < 4; a++) c[r][a] += rv[r]*av[a];
            }
            #pragma unroll
            for (int r = 0; r < 8; r++) {
                *(float4*)&g_Er[((size_t)bh*NT_ + u0 + ub + r)*N_ + ib] =
                    make_float4(c[r][0], c[r][1], c[r][2], c[r][3]);
            }
        }
    }
}

// ---------------- K2: masked attention core ----------------
// grid (128, 8): x encodes (tt descending, h); 256 threads; 2 CTAs/SM
#define K2_SMEM_FLOATS (64*132 + 64*68 + 64*68 + 64*132)
#define K2_SMEM (K2_SMEM_FLOATS * 4)

__global__ __launch_bounds__(256, 2) void k2_kernel(const float* __restrict__ R) {
    extern __shared__ float sm[];
    float* sRt = sm;              // [i][t] 64 x 132
    float* sQr = sRt + 64*132;    // [i][u] 64 x 68
    float* sEr = sQr + 64*68;     // [u][i] 64 x 68
    float* sS  = sEr + 64*68;     // [u][t] 64 x 132
    const int tid = threadIdx.x;
    const int b   = blockIdx.y;
    const int x   = blockIdx.x;
    const int tt  = 15 - (x >> 3);   // big tiles scheduled first
    const int h   = x & 7;
    const int t0  = tt * 128;
    const int bh  = b*NH_ + h;

    // Load R[b, t0..t0+127, :] transposed into sRt[i][t]
    for (int p = tid; p < 128*16; p += 256) {
        int t = p >> 4, i4 = (p & 15) << 2;
        float4 v = *(const float4*)&R[((size_t)b*NT_ + t0 + t)*N_ + i4];
        sRt[(i4+0)*132 + t] = v.x;
        sRt[(i4+1)*132 + t] = v.y;
        sRt[(i4+2)*132 + t] = v.z;
        sRt[(i4+3)*132 + t] = v.w;
    }

    const int tg = tid >> 4;          // t microtile group (16 groups of 8)
    const int lo = tid & 15;          // u or i microtile group
    const int tb = tg * 8;

    float acc[8][4];
    #pragma unroll
    for (int r = 0; r < 8; r++)
        #pragma unroll
        for (int a = 0; a < 4; a++) acc[r][a] = 0.f;

    const int nU = (tt + 1) * 2;      // 64-wide u-tiles with u <= t
    for (int ut = 0; ut < nU; ut++) {
        const int u0 = ut * 64;
        __syncthreads();  // prior GEMM2 done reading sS/sEr; safe to refill
        for (int p = tid; p < 64*16; p += 256) {
            int r = p >> 4, c4 = (p & 15) << 2;
            *(float4*)&sQr[r*68 + c4] =
                *(const float4*)&g_QrT[((size_t)bh*N_ + r)*NT_ + u0 + c4];
            *(float4*)&sEr[r*68 + c4] =
                *(const float4*)&g_Er [((size_t)bh*NT_ + u0 + r)*N_ + c4];
        }
        __syncthreads();

        // GEMM1: S[t][u] = sum_i sRt[i][t] * sQr[i][u]   (8t x 4u microtile)
        {
            const int ub = lo * 4;
            float c[8][4];
            #pragma unroll
            for (int r = 0; r < 8; r++)
                #pragma unroll
                for (int a = 0; a < 4; a++) c[r][a] = 0.f;
            #pragma unroll 8
            for (int i = 0; i < 64; i++) {
                float4 r0 = *(const float4*)&sRt[i*132 + tb];
                float4 r1 = *(const float4*)&sRt[i*132 + tb + 4];
                float4 qv = *(const float4*)&sQr[i*68 + ub];
                float tv[8] = {r0.x, r0.y, r0.z, r0.w, r1.x, r1.y, r1.z, r1.w};
                float uv[4] = {qv.x, qv.y, qv.z, qv.w};
                #pragma unroll
                for (int r = 0; r < 8; r++)
                    #pragma unroll
                    for (int a = 0; a < 4; a++) c[r][a] += tv[r]*uv[a];
            }
            // causal mask (only diagonal-straddling tiles), store S transposed
            const bool needMask = (u0 + 63 > t0);
            #pragma unroll
            for (int uu = 0; uu < 4; uu++) {
                if (needMask) {
                    const int ug = u0 + lo*4 + uu;
                    #pragma unroll
                    for (int r = 0; r < 8; r++)
                        if (ug > t0 + tb + r) c[r][uu] = 0.f;
                }
                *(float4*)&sS[(lo*4+uu)*132 + tb] =
                    make_float4(c[0][uu], c[1][uu], c[2][uu], c[3][uu]);
                *(float4*)&sS[(lo*4+uu)*132 + tb + 4] =
                    make_float4(c[4][uu], c[5][uu], c[6][uu], c[7][uu]);
            }
        }
        __syncthreads();

        // GEMM2: acc[t][i] += sum_u sS[u][t] * sEr[u][i]  (8t x 4i microtile)
        {
            const int ib = lo * 4;
            #pragma unroll 8
            for (int u = 0; u < 64; u++) {
                float4 s0 = *(const float4*)&sS [u*132 + tb];
                float4 s1 = *(const float4*)&sS [u*132 + tb + 4];
                float4 ev = *(const float4*)&sEr[u*68 + ib];
                float sv[8] = {s0.x, s0.y, s0.z, s0.w, s1.x, s1.y, s1.z, s1.w};
                float evv[4] = {ev.x, ev.y, ev.z, ev.w};
                #pragma unroll
                for (int r = 0; r < 8; r++)
                    #pragma unroll
                    for (int a = 0; a < 4; a++) acc[r][a] += sv[r]*evv[a];
            }
        }
    }

    // Write per-h partial
    {
        const int ib = lo * 4;
        #pragma unroll
        for (int r = 0; r < 8; r++) {
            *(float4*)&g_part[((size_t)bh*NT_ + t0 + tb + r)*N_ + ib] =
                make_float4(acc[r][0], acc[r][1], acc[r][2], acc[r][3]);
        }
    }
}

// ---------------- K3: reduce over h ----------------
__global__ __launch_bounds__(256) void k3_kernel(float* __restrict__ out) {
    const int v = blockIdx.x * 256 + threadIdx.x;    // over D*NT*N/4 float4s
    const int b = v >> 15;                           // 2048*16 float4 per b
    const int r = v & 32767;
    const float4* p4 = (const float4*)g_part;
    float4 s = make_float4(0.f, 0.f, 0.f, 0.f);
    #pragma unroll
    for (int h = 0; h < NH_; h++) {
        float4 p = p4[((size_t)(b*NH_ + h) << 15) + r];
        s.x += p.x; s.y += p.y; s.z += p.z; s.w += p.w;
    }
    ((float4*)out)[v] = s;
}

extern "C" void kernel_launch(void* const* d_in, const int* in_sizes, int n_in,
                              void* d_out, int out_size) {
    const float* R = (const float*)d_in[0];  // r_prime (8,2048,64)
    const float* Q = (const float*)d_in[1];  // (8,64,64)
    const float* E = (const float*)d_in[2];  // (8,64,64)
    float* out = (float*)d_out;

    cudaFuncSetAttribute(k1_kernel, cudaFuncAttributeMaxDynamicSharedMemorySize, K1_SMEM);
    cudaFuncSetAttribute(k2_kernel, cudaFuncAttributeMaxDynamicSharedMemorySize, K2_SMEM);

    k1_kernel<<<dim3(16, D_), 256, K1_SMEM>>>(R, Q, E);
    k2_kernel<<<dim3(128, D_), 256, K2_SMEM>>>(R);
    k3_kernel<<<(D_*NT_*N_/4) / 256, 256>>>(out);
}

// round 4
// speedup vs baseline: 2.6215x; 2.6215x over previous
#include <cuda_runtime.h>
#include <cuda_bf16.h>
#include <cstdint>

#define D_  8
#define NT_ 2048
#define N_  64
#define NH_ 8

// ---------------- device scratch (allocation-free) ----------------
__device__ __align__(16) __nv_bfloat16 g_Rhi[D_*NT_*N_];
__device__ __align__(16) __nv_bfloat16 g_Rlo[D_*NT_*N_];
__device__ __align__(16) __nv_bfloat16 g_Qhi[(size_t)D_*NH_*NT_*N_]; // [bh][u][i]
__device__ __align__(16) __nv_bfloat16 g_Qlo[(size_t)D_*NH_*NT_*N_];
__device__ __align__(16) __nv_bfloat16 g_Ehi[(size_t)D_*NH_*N_*NT_]; // [bh][i][u]
__device__ __align__(16) __nv_bfloat16 g_Elo[(size_t)D_*NH_*N_*NT_];
__device__ __align__(16) float g_part[(size_t)D_*NH_*NT_*N_];        // [bh][t][i]

// ---------------- helpers ----------------
__device__ __forceinline__ uint32_t smem_u32(const void* p) {
    uint32_t a;
    asm("{ .reg .u64 t; cvta.to.shared.u64 t, %1; cvt.u32.u64 %0, t; }" : "=r"(a) : "l"(p));
    return a;
}
#define SWZ(o) ((o) ^ (((o) >> 3) & 0x70))

#define CP16(s, g) asm volatile("cp.async.ca.shared.global [%0], [%1], 16;" :: "r"(s), "l"(g) : "memory")
#define CP_COMMIT() asm volatile("cp.async.commit_group;" ::: "memory")
#define CP_WAIT0()  asm volatile("cp.async.wait_group 0;" ::: "memory")

__device__ __forceinline__ void ldm4(uint32_t* r, uint32_t addr) {
    asm volatile("ldmatrix.sync.aligned.m8n8.x4.shared.b16 {%0,%1,%2,%3}, [%4];"
        : "=r"(r[0]), "=r"(r[1]), "=r"(r[2]), "=r"(r[3]) : "r"(addr));
}
__device__ __forceinline__ void hmma(float* c, const uint32_t* a, uint32_t b0, uint32_t b1) {
    asm("mma.sync.aligned.m16n8k16.row.col.f32.bf16.bf16.f32 "
        "{%0,%1,%2,%3},{%4,%5,%6,%7},{%8,%9},{%0,%1,%2,%3};"
        : "+f"(c[0]), "+f"(c[1]), "+f"(c[2]), "+f"(c[3])
        : "r"(a[0]), "r"(a[1]), "r"(a[2]), "r"(a[3]), "r"(b0), "r"(b1));
}
__device__ __forceinline__ void bsplit(float f, unsigned short& h, unsigned short& l) {
    __nv_bfloat16 hb = __float2bfloat16_rn(f);
    float rem = f - __bfloat162float(hb);
    __nv_bfloat16 lb = __float2bfloat16_rn(rem);
    h = __bfloat16_as_ushort(hb);
    l = __bfloat16_as_ushort(lb);
}
__device__ __forceinline__ void split2(float f0, float f1, uint32_t& hi, uint32_t& lo) {
    unsigned short h0, h1, l0, l1;
    bsplit(f0, h0, l0); bsplit(f1, h1, l1);
    hi = ((uint32_t)h1 << 16) | h0;
    lo = ((uint32_t)l1 << 16) | l0;
}

// ---------------- K0: split R into bf16 hi/lo ----------------
__global__ __launch_bounds__(256) void k0_kernel(const float* __restrict__ R) {
    const int idx = blockIdx.x * 256 + threadIdx.x;       // 262144 float4s
    float4 v = ((const float4*)R)[idx];
    unsigned short h0,h1,h2,h3,l0,l1,l2,l3;
    bsplit(v.x,h0,l0); bsplit(v.y,h1,l1); bsplit(v.z,h2,l2); bsplit(v.w,h3,l3);
    ((uint2*)g_Rhi)[idx] = make_uint2(((uint32_t)h1<<16)|h0, ((uint32_t)h3<<16)|h2);
    ((uint2*)g_Rlo)[idx] = make_uint2(((uint32_t)l1<<16)|l0, ((uint32_t)l3<<16)|l2);
}

// ---------------- K1: Qr[u,i], ErT[i,u] fp32 -> bf16 hi/lo ----------------
#define K1_SMEM ((64*132 + 2*64*68) * 4)

__global__ __launch_bounds__(256) void k1_kernel(const float* __restrict__ R,
                                                 const float* __restrict__ Q,
                                                 const float* __restrict__ E) {
    extern __shared__ float sm[];
    float* sR  = sm;              // [j][u] 64 x 132
    float* sQT = sR + 64*132;     // [j][i] 64 x 68
    float* sET = sQT + 64*68;     // [j][i] 64 x 68
    const int tid = threadIdx.x;
    const int b = blockIdx.y, h = blockIdx.z;
    const int u0 = blockIdx.x * 128;

    for (int p = tid; p < 128*16; p += 256) {
        int u = p >> 4, j4 = (p & 15) << 2;
        float4 v = *(const float4*)&R[((size_t)b*NT_ + u0 + u)*N_ + j4];
        sR[(j4+0)*132+u]=v.x; sR[(j4+1)*132+u]=v.y; sR[(j4+2)*132+u]=v.z; sR[(j4+3)*132+u]=v.w;
    }
    for (int p = tid; p < 64*16; p += 256) {
        int i = p >> 4, j4 = (p & 15) << 2;
        float4 q = *(const float4*)&Q[((size_t)h*N_ + i)*N_ + j4];
        float4 e = *(const float4*)&E[((size_t)h*N_ + i)*N_ + j4];
        sQT[(j4+0)*68+i]=q.x; sQT[(j4+1)*68+i]=q.y; sQT[(j4+2)*68+i]=q.z; sQT[(j4+3)*68+i]=q.w;
        sET[(j4+0)*68+i]=e.x; sET[(j4+1)*68+i]=e.y; sET[(j4+2)*68+i]=e.z; sET[(j4+3)*68+i]=e.w;
    }
    __syncthreads();

    const int bh = b*NH_ + h;
    const int ug = tid >> 4, ig = tid & 15;
    const int ub = ug * 8, ib = ig * 4;
    float cq[8][4], ce[8][4];
    #pragma unroll
    for (int r = 0; r < 8; r++)
        #pragma unroll
        for (int a = 0; a < 4; a++) { cq[r][a] = 0.f; ce[r][a] = 0.f; }

    #pragma unroll 8
    for (int j = 0; j < 64; j++) {
        float4 r0 = *(const float4*)&sR [j*132 + ub];
        float4 r1 = *(const float4*)&sR [j*132 + ub + 4];
        float4 qv = *(const float4*)&sQT[j*68 + ib];
        float4 ev = *(const float4*)&sET[j*68 + ib];
        float rv[8] = {r0.x, r0.y, r0.z, r0.w, r1.x, r1.y, r1.z, r1.w};
        float qa[4] = {qv.x, qv.y, qv.z, qv.w};
        float ea[4] = {ev.x, ev.y, ev.z, ev.w};
        #pragma unroll
        for (int r = 0; r < 8; r++)
            #pragma unroll
            for (int a = 0; a < 4; a++) { cq[r][a] += rv[r]*qa[a]; ce[r][a] += rv[r]*ea[a]; }
    }

    #pragma unroll
    for (int r = 0; r < 8; r++) {
        unsigned short h0,h1,h2,h3,l0,l1,l2,l3;
        bsplit(cq[r][0],h0,l0); bsplit(cq[r][1],h1,l1);
        bsplit(cq[r][2],h2,l2); bsplit(cq[r][3],h3,l3);
        size_t o = ((size_t)bh*NT_ + u0 + ub + r)*N_ + ib;
        *(uint2*)&g_Qhi[o] = make_uint2(((uint32_t)h1<<16)|h0, ((uint32_t)h3<<16)|h2);
        *(uint2*)&g_Qlo[o] = make_uint2(((uint32_t)l1<<16)|l0, ((uint32_t)l3<<16)|l2);
    }
    #pragma unroll
    for (int a = 0; a < 4; a++) {
        unsigned short hh[8], ll[8];
        #pragma unroll
        for (int r = 0; r < 8; r++) bsplit(ce[r][a], hh[r], ll[r]);
        size_t o = ((size_t)bh*N_ + ib + a)*NT_ + u0 + ub;
        *(uint4*)&g_Ehi[o] = make_uint4(((uint32_t)hh[1]<<16)|hh[0], ((uint32_t)hh[3]<<16)|hh[2],
                                        ((uint32_t)hh[5]<<16)|hh[4], ((uint32_t)hh[7]<<16)|hh[6]);
        *(uint4*)&g_Elo[o] = make_uint4(((uint32_t)ll[1]<<16)|ll[0], ((uint32_t)ll[3]<<16)|ll[2],
                                        ((uint32_t)ll[5]<<16)|ll[4], ((uint32_t)ll[7]<<16)|ll[6]);
    }
}

// ---------------- K2: HMMA masked attention core ----------------
#define OFF_QH 0
#define OFF_QL 8192
#define OFF_EH 16384
#define OFF_EL 24576
#define STAGE  32768
#define K2_SMEM (2*STAGE)

__device__ __forceinline__ void load_stage(uint32_t sbase, int bh, int u0, int tid) {
    const char* q_h = (const char*)g_Qhi + (((size_t)bh*NT_ + u0)*N_)*2;
    const char* q_l = (const char*)g_Qlo + (((size_t)bh*NT_ + u0)*N_)*2;
    const char* e_h = (const char*)g_Ehi + (((size_t)bh*N_)*NT_ + u0)*2;
    const char* e_l = (const char*)g_Elo + (((size_t)bh*N_)*NT_ + u0)*2;
    #pragma unroll
    for (int qd = 0; qd < 4; qd++) {
        int c   = tid + qd*128;            // 0..511 16B chunks
        int row = c >> 3, ch = (c & 7) * 16;
        int off = row*128 + ch;
        int sw  = SWZ(off);
        CP16(sbase + OFF_QH + sw, q_h + off);
        CP16(sbase + OFF_QL + sw, q_l + off);
        CP16(sbase + OFF_EH + sw, e_h + (size_t)row*(NT_*2) + ch);
        CP16(sbase + OFF_EL + sw, e_l + (size_t)row*(NT_*2) + ch);
    }
}

__global__ __launch_bounds__(128, 2) void k2_kernel() {
    extern __shared__ char smem[];
    const uint32_t smem_base = smem_u32(smem);
    const int tid  = threadIdx.x;
    const int w    = tid >> 5, lane = tid & 31;
    const int gid  = lane >> 2, tig = lane & 3;
    const int b    = blockIdx.y, x = blockIdx.x;
    const int tt   = 15 - (x >> 3), h = x & 7;     // big tiles first
    const int t0   = tt * 128;
    const int bh   = b*NH_ + h;
    const int trow = t0 + 32*w;

    // R A-fragments (held in registers for the whole block)
    uint32_t Ah[2][4][4], Al[2][4][4];
    #pragma unroll
    for (int mt = 0; mt < 2; mt++) {
        size_t r0 = ((size_t)b*NT_ + trow + 16*mt + gid)*N_;
        size_t r1 = r0 + 8*N_;
        #pragma unroll
        for (int kk = 0; kk < 4; kk++) {
            int c0 = 16*kk + 2*tig, c1 = c0 + 8;
            Ah[mt][kk][0] = *(const uint32_t*)((const char*)g_Rhi + (r0 + c0)*2);
            Ah[mt][kk][1] = *(const uint32_t*)((const char*)g_Rhi + (r1 + c0)*2);
            Ah[mt][kk][2] = *(const uint32_t*)((const char*)g_Rhi + (r0 + c1)*2);
            Ah[mt][kk][3] = *(const uint32_t*)((const char*)g_Rhi + (r1 + c1)*2);
            Al[mt][kk][0] = *(const uint32_t*)((const char*)g_Rlo + (r0 + c0)*2);
            Al[mt][kk][1] = *(const uint32_t*)((const char*)g_Rlo + (r1 + c0)*2);
            Al[mt][kk][2] = *(const uint32_t*)((const char*)g_Rlo + (r0 + c1)*2);
            Al[mt][kk][3] = *(const uint32_t*)((const char*)g_Rlo + (r1 + c1)*2);
        }
    }

    float O[2][8][4];
    #pragma unroll
    for (int mt = 0; mt < 2; mt++)
        #pragma unroll
        for (int n = 0; n < 8; n++)
            #pragma unroll
            for (int a = 0; a < 4; a++) O[mt][n][a] = 0.f;

    const int nU = (tt + 1) * 2;
    load_stage(smem_base, bh, 0, tid);
    CP_COMMIT();

    const int rowA = lane & 15, hi16 = (lane >> 4) << 4;

    for (int ut = 0; ut < nU; ut++) {
        const int u0 = ut * 64;
        CP_WAIT0();
        __syncthreads();
        if (ut + 1 < nU) {
            load_stage(smem_base + ((ut+1)&1)*STAGE, bh, u0 + 64, tid);
            CP_COMMIT();
        }
        const uint32_t sb  = smem_base + (ut&1)*STAGE;
        const uint32_t sQh = sb + OFF_QH, sQl = sb + OFF_QL;
        const uint32_t sEh = sb + OFF_EH, sEl = sb + OFF_EL;

        float S[2][8][4];
        #pragma unroll
        for (int mt = 0; mt < 2; mt++)
            #pragma unroll
            for (int n = 0; n < 8; n++)
                #pragma unroll
                for (int a = 0; a < 4; a++) S[mt][n][a] = 0.f;

        // MMA1: S[t,u] = sum_i R[t,i] * Qr[u,i]   (3 bf16 products)
        #pragma unroll
        for (int jj = 0; jj < 4; jj++) {
            #pragma unroll
            for (int kk = 0; kk < 4; kk++) {
                int off = (16*jj + rowA)*128 + 32*kk + hi16;
                int sw  = SWZ(off);
                uint32_t qh[4], ql[4];
                ldm4(qh, sQh + sw);
                ldm4(ql, sQl + sw);
                hmma(S[0][2*jj],   Ah[0][kk], qh[0], qh[2]);
                hmma(S[0][2*jj+1], Ah[0][kk], qh[1], qh[3]);
                hmma(S[1][2*jj],   Ah[1][kk], qh[0], qh[2]);
                hmma(S[1][2*jj+1], Ah[1][kk], qh[1], qh[3]);
                hmma(S[0][2*jj],   Al[0][kk], qh[0], qh[2]);
                hmma(S[0][2*jj+1], Al[0][kk], qh[1], qh[3]);
                hmma(S[1][2*jj],   Al[1][kk], qh[0], qh[2]);
                hmma(S[1][2*jj+1], Al[1][kk], qh[1], qh[3]);
                hmma(S[0][2*jj],   Ah[0][kk], ql[0], ql[2]);
                hmma(S[0][2*jj+1], Ah[0][kk], ql[1], ql[3]);
                hmma(S[1][2*jj],   Ah[1][kk], ql[0], ql[2]);
                hmma(S[1][2*jj+1], Ah[1][kk], ql[1], ql[3]);
            }
        }

        // causal mask in C fragments
        #pragma unroll
        for (int mt = 0; mt < 2; mt++) {
            const int tA = trow + 16*mt + gid, tB = tA + 8;
            if (u0 + 63 > trow + 16*mt) {
                #pragma unroll
                for (int n = 0; n < 8; n++) {
                    const int uA = u0 + 8*n + 2*tig, uB = uA + 1;
                    if (uA > tA) S[mt][n][0] = 0.f;
                    if (uB > tA) S[mt][n][1] = 0.f;
                    if (uA > tB) S[mt][n][2] = 0.f;
                    if (uB > tB) S[mt][n][3] = 0.f;
                }
            }
        }

        // split S -> bf16 hi/lo A-fragments, MMA2: O[t,i] += S[t,u] * ErT[i,u]
        #pragma unroll
        for (int kk = 0; kk < 4; kk++) {
            uint32_t a2h[2][4], a2l[2][4];
            #pragma unroll
            for (int mt = 0; mt < 2; mt++) {
                split2(S[mt][2*kk][0],   S[mt][2*kk][1],   a2h[mt][0], a2l[mt][0]);
                split2(S[mt][2*kk][2],   S[mt][2*kk][3],   a2h[mt][1], a2l[mt][1]);
                split2(S[mt][2*kk+1][0], S[mt][2*kk+1][1], a2h[mt][2], a2l[mt][2]);
                split2(S[mt][2*kk+1][2], S[mt][2*kk+1][3], a2h[mt][3], a2l[mt][3]);
            }
            #pragma unroll
            for (int jj = 0; jj < 4; jj++) {
                int off = (16*jj + rowA)*128 + 32*kk + hi16;
                int sw  = SWZ(off);
                uint32_t eh[4], el[4];
                ldm4(eh, sEh + sw);
                ldm4(el, sEl + sw);
                hmma(O[0][2*jj],   a2h[0], eh[0], eh[2]);
                hmma(O[0][2*jj+1], a2h[0], eh[1], eh[3]);
                hmma(O[1][2*jj],   a2h[1], eh[0], eh[2]);
                hmma(O[1][2*jj+1], a2h[1], eh[1], eh[3]);
                hmma(O[0][2*jj],   a2l[0], eh[0], eh[2]);
                hmma(O[0][2*jj+1], a2l[0], eh[1], eh[3]);
                hmma(O[1][2*jj],   a2l[1], eh[0], eh[2]);
                hmma(O[1][2*jj+1], a2l[1], eh[1], eh[3]);
                hmma(O[0][2*jj],   a2h[0], el[0], el[2]);
                hmma(O[0][2*jj+1], a2h[0], el[1], el[3]);
                hmma(O[1][2*jj],   a2h[1], el[0], el[2]);
                hmma(O[1][2*jj+1], a2h[1], el[1], el[3]);
            }
        }
    }

    // store per-h partial
    #pragma unroll
    for (int mt = 0; mt < 2; mt++) {
        const int tA = trow + 16*mt + gid;
        #pragma unroll
        for (int n = 0; n < 8; n++) {
            const int col = 8*n + 2*tig;
            *(float2*)&g_part[((size_t)bh*NT_ + tA    )*N_ + col] = make_float2(O[mt][n][0], O[mt][n][1]);
            *(float2*)&g_part[((size_t)bh*NT_ + tA + 8)*N_ + col] = make_float2(O[mt][n][2], O[mt][n][3]);
        }
    }
}

// ---------------- K3: reduce over h ----------------
__global__ __launch_bounds__(256) void k3_kernel(float* __restrict__ out) {
    const int v = blockIdx.x * 256 + threadIdx.x;
    const int b = v >> 15;
    const int r = v & 32767;
    const float4* p4 = (const float4*)g_part;
    float4 s = make_float4(0.f, 0.f, 0.f, 0.f);
    #pragma unroll
    for (int h = 0; h < NH_; h++) {
        float4 p = p4[((size_t)(b*NH_ + h) << 15) + r];
        s.x += p.x; s.y += p.y; s.z += p.z; s.w += p.w;
    }
    ((float4*)out)[v] = s;
}

extern "C" void kernel_launch(void* const* d_in, const int* in_sizes, int n_in,
                              void* d_out, int out_size) {
    const float* R = (const float*)d_in[0];
    const float* Q = (const float*)d_in[1];
    const float* E = (const float*)d_in[2];
    float* out = (float*)d_out;

    cudaFuncSetAttribute(k1_kernel, cudaFuncAttributeMaxDynamicSharedMemorySize, K1_SMEM);
    cudaFuncSetAttribute(k2_kernel, cudaFuncAttributeMaxDynamicSharedMemorySize, K2_SMEM);

    k0_kernel<<<1024, 256>>>(R);
    k1_kernel<<<dim3(16, D_, NH_), 256, K1_SMEM>>>(R, Q, E);
    k2_kernel<<<dim3(128, D_), 128, K2_SMEM>>>();
    k3_kernel<<<(D_*NT_*N_/4) / 256, 256>>>(out);
}

// round 5
// speedup vs baseline: 2.8691x; 1.0945x over previous
#include <cuda_runtime.h>
#include <cuda_bf16.h>
#include <cstdint>

#define D_  8
#define NT_ 2048
#define N_  64
#define NH_ 8

// ---------------- device scratch (allocation-free) ----------------
__device__ __align__(16) __nv_bfloat16 g_Rhi[D_*NT_*N_];
__device__ __align__(16) __nv_bfloat16 g_Rlo[D_*NT_*N_];
__device__ __align__(16) __nv_bfloat16 g_Qhi[(size_t)D_*NH_*NT_*N_]; // [bh][u][i]
__device__ __align__(16) __nv_bfloat16 g_Qlo[(size_t)D_*NH_*NT_*N_];
__device__ __align__(16) __nv_bfloat16 g_Ehi[(size_t)D_*NH_*N_*NT_]; // [bh][i][u]
__device__ __align__(16) __nv_bfloat16 g_Elo[(size_t)D_*NH_*N_*NT_];
__device__ __align__(16) float g_part[(size_t)D_*NH_*NT_*N_];        // [bh][t][i]

// ---------------- helpers ----------------
__device__ __forceinline__ uint32_t smem_u32(const void* p) {
    uint32_t a;
    asm("{ .reg .u64 t; cvta.to.shared.u64 t, %1; cvt.u32.u64 %0, t; }" : "=r"(a) : "l"(p));
    return a;
}
#define SWZ(o) ((o) ^ (((o) >> 3) & 0x70))

#define CP16(s, g) asm volatile("cp.async.ca.shared.global [%0], [%1], 16;" :: "r"(s), "l"(g) : "memory")
#define CP_COMMIT() asm volatile("cp.async.commit_group;" ::: "memory")
#define CP_WAIT1()  asm volatile("cp.async.wait_group 1;" ::: "memory")

__device__ __forceinline__ void ldm4(uint32_t* r, uint32_t addr) {
    asm volatile("ldmatrix.sync.aligned.m8n8.x4.shared.b16 {%0,%1,%2,%3}, [%4];"
        : "=r"(r[0]), "=r"(r[1]), "=r"(r[2]), "=r"(r[3]) : "r"(addr));
}
__device__ __forceinline__ void hmma(float* c, const uint32_t* a, uint32_t b0, uint32_t b1) {
    asm("mma.sync.aligned.m16n8k16.row.col.f32.bf16.bf16.f32 "
        "{%0,%1,%2,%3},{%4,%5,%6,%7},{%8,%9},{%0,%1,%2,%3};"
        : "+f"(c[0]), "+f"(c[1]), "+f"(c[2]), "+f"(c[3])
        : "r"(a[0]), "r"(a[1]), "r"(a[2]), "r"(a[3]), "r"(b0), "r"(b1));
}
// fast truncation split: f = hi + lo exactly in fp32; hi = trunc-to-bf16, lo -> bf16 rn.
// packs two elements: hi = {f1.hi16, f0.hi16}, lo = bf16x2(lo1, lo0)
__device__ __forceinline__ void split2(float f0, float f1, uint32_t& hi, uint32_t& lo) {
    uint32_t u0 = __float_as_uint(f0) & 0xFFFF0000u;
    uint32_t u1 = __float_as_uint(f1) & 0xFFFF0000u;
    hi = __byte_perm(u0, u1, 0x7632);
    float l0 = f0 - __uint_as_float(u0);
    float l1 = f1 - __uint_as_float(u1);
    asm("cvt.rn.bf16x2.f32 %0, %1, %2;" : "=r"(lo) : "f"(l1), "f"(l0));
}

// ---------------- K0: split R into bf16 hi/lo ----------------
__global__ __launch_bounds__(256) void k0_kernel(const float* __restrict__ R) {
    const int idx = blockIdx.x * 256 + threadIdx.x;       // 262144 float4s
    float4 v = ((const float4*)R)[idx];
    uint32_t h01, l01, h23, l23;
    split2(v.x, v.y, h01, l01);
    split2(v.z, v.w, h23, l23);
    ((uint2*)g_Rhi)[idx] = make_uint2(h01, h23);
    ((uint2*)g_Rlo)[idx] = make_uint2(l01, l23);
}

// ---------------- K1: Qr[u,i], ErT[i,u] fp32 -> bf16 hi/lo ----------------
#define K1_SMEM ((64*132 + 2*64*68) * 4)

__global__ __launch_bounds__(256) void k1_kernel(const float* __restrict__ R,
                                                 const float* __restrict__ Q,
                                                 const float* __restrict__ E) {
    extern __shared__ float sm[];
    float* sR  = sm;              // [j][u] 64 x 132
    float* sQT = sR + 64*132;     // [j][i] 64 x 68
    float* sET = sQT + 64*68;     // [j][i] 64 x 68
    const int tid = threadIdx.x;
    const int b = blockIdx.y, h = blockIdx.z;
    const int u0 = blockIdx.x * 128;

    for (int p = tid; p < 128*16; p += 256) {
        int u = p >> 4, j4 = (p & 15) << 2;
        float4 v = *(const float4*)&R[((size_t)b*NT_ + u0 + u)*N_ + j4];
        sR[(j4+0)*132+u]=v.x; sR[(j4+1)*132+u]=v.y; sR[(j4+2)*132+u]=v.z; sR[(j4+3)*132+u]=v.w;
    }
    for (int p = tid; p < 64*16; p += 256) {
        int i = p >> 4, j4 = (p & 15) << 2;
        float4 q = *(const float4*)&Q[((size_t)h*N_ + i)*N_ + j4];
        float4 e = *(const float4*)&E[((size_t)h*N_ + i)*N_ + j4];
        sQT[(j4+0)*68+i]=q.x; sQT[(j4+1)*68+i]=q.y; sQT[(j4+2)*68+i]=q.z; sQT[(j4+3)*68+i]=q.w;
        sET[(j4+0)*68+i]=e.x; sET[(j4+1)*68+i]=e.y; sET[(j4+2)*68+i]=e.z; sET[(j4+3)*68+i]=e.w;
    }
    __syncthreads();

    const int bh = b*NH_ + h;
    const int ug = tid >> 4, ig = tid & 15;
    const int ub = ug * 8, ib = ig * 4;
    float cq[8][4], ce[8][4];
    #pragma unroll
    for (int r = 0; r < 8; r++)
        #pragma unroll
        for (int a = 0; a < 4; a++) { cq[r][a] = 0.f; ce[r][a] = 0.f; }

    #pragma unroll 8
    for (int j = 0; j < 64; j++) {
        float4 r0 = *(const float4*)&sR [j*132 + ub];
        float4 r1 = *(const float4*)&sR [j*132 + ub + 4];
        float4 qv = *(const float4*)&sQT[j*68 + ib];
        float4 ev = *(const float4*)&sET[j*68 + ib];
        float rv[8] = {r0.x, r0.y, r0.z, r0.w, r1.x, r1.y, r1.z, r1.w};
        float qa[4] = {qv.x, qv.y, qv.z, qv.w};
        float ea[4] = {ev.x, ev.y, ev.z, ev.w};
        #pragma unroll
        for (int r = 0; r < 8; r++)
            #pragma unroll
            for (int a = 0; a < 4; a++) { cq[r][a] += rv[r]*qa[a]; ce[r][a] += rv[r]*ea[a]; }
    }

    // Qr[u,i] hi/lo (pairs along i)
    #pragma unroll
    for (int r = 0; r < 8; r++) {
        uint32_t hA, lA, hB, lB;
        split2(cq[r][0], cq[r][1], hA, lA);
        split2(cq[r][2], cq[r][3], hB, lB);
        size_t o = ((size_t)bh*NT_ + u0 + ub + r)*N_ + ib;
        *(uint2*)&g_Qhi[o] = make_uint2(hA, hB);
        *(uint2*)&g_Qlo[o] = make_uint2(lA, lB);
    }
    // ErT[i,u] hi/lo (pairs along u = r dimension)
    #pragma unroll
    for (int a = 0; a < 4; a++) {
        uint32_t hh[4], ll[4];
        #pragma unroll
        for (int pr = 0; pr < 4; pr++)
            split2(ce[2*pr][a], ce[2*pr+1][a], hh[pr], ll[pr]);
        size_t o = ((size_t)bh*N_ + ib + a)*NT_ + u0 + ub;
        *(uint4*)&g_Ehi[o] = make_uint4(hh[0], hh[1], hh[2], hh[3]);
        *(uint4*)&g_Elo[o] = make_uint4(ll[0], ll[1], ll[2], ll[3]);
    }
}

// ---------------- K2: HMMA masked attention core ----------------
// 256 threads = 8 warps, one m16 tile per warp; 3-stage cp.async pipeline.
#define OFF_QH 0
#define OFF_QL 8192
#define OFF_EH 16384
#define OFF_EL 24576
#define STAGE  32768
#define K2_SMEM (3*STAGE)

__device__ __forceinline__ void load_stage(uint32_t sbase, int bh, int u0, int tid) {
    const char* q_h = (const char*)g_Qhi + (((size_t)bh*NT_ + u0)*N_)*2;
    const char* q_l = (const char*)g_Qlo + (((size_t)bh*NT_ + u0)*N_)*2;
    const char* e_h = (const char*)g_Ehi + (((size_t)bh*N_)*NT_ + u0)*2;
    const char* e_l = (const char*)g_Elo + (((size_t)bh*N_)*NT_ + u0)*2;
    #pragma unroll
    for (int qd = 0; qd < 2; qd++) {
        int c   = tid + qd*256;            // 0..511 16B chunks
        int row = c >> 3, ch = (c & 7) * 16;
        int off = row*128 + ch;
        int sw  = SWZ(off);
        CP16(sbase + OFF_QH + sw, q_h + off);
        CP16(sbase + OFF_QL + sw, q_l + off);
        CP16(sbase + OFF_EH + sw, e_h + (size_t)row*(NT_*2) + ch);
        CP16(sbase + OFF_EL + sw, e_l + (size_t)row*(NT_*2) + ch);
    }
}

__global__ __launch_bounds__(256, 1) void k2_kernel() {
    extern __shared__ char smem[];
    const uint32_t smem_base = smem_u32(smem);
    const int tid  = threadIdx.x;
    const int w    = tid >> 5, lane = tid & 31;
    const int gid  = lane >> 2, tig = lane & 3;
    const int b    = blockIdx.y, x = blockIdx.x;
    const int tt   = 15 - (x >> 3), h = x & 7;     // big tiles first
    const int t0   = tt * 128;
    const int bh   = b*NH_ + h;
    const int trow = t0 + 16*w;                    // this warp's m16 tile

    // R A-fragments (registers for whole block): Ah/Al[kk][4]
    uint32_t Ah[4][4], Al[4][4];
    {
        size_t r0 = ((size_t)b*NT_ + trow + gid)*N_;
        size_t r1 = r0 + 8*N_;
        #pragma unroll
        for (int kk = 0; kk < 4; kk++) {
            int c0 = 16*kk + 2*tig, c1 = c0 + 8;
            Ah[kk][0] = *(const uint32_t*)((const char*)g_Rhi + (r0 + c0)*2);
            Ah[kk][1] = *(const uint32_t*)((const char*)g_Rhi + (r1 + c0)*2);
            Ah[kk][2] = *(const uint32_t*)((const char*)g_Rhi + (r0 + c1)*2);
            Ah[kk][3] = *(const uint32_t*)((const char*)g_Rhi + (r1 + c1)*2);
            Al[kk][0] = *(const uint32_t*)((const char*)g_Rlo + (r0 + c0)*2);
            Al[kk][1] = *(const uint32_t*)((const char*)g_Rlo + (r1 + c0)*2);
            Al[kk][2] = *(const uint32_t*)((const char*)g_Rlo + (r0 + c1)*2);
            Al[kk][3] = *(const uint32_t*)((const char*)g_Rlo + (r1 + c1)*2);
        }
    }

    float O[8][4];
    #pragma unroll
    for (int n = 0; n < 8; n++)
        #pragma unroll
        for (int a = 0; a < 4; a++) O[n][a] = 0.f;

    const int nU = (tt + 1) * 2;       // >= 2
    load_stage(smem_base, bh, 0, tid);
    CP_COMMIT();
    load_stage(smem_base + STAGE, bh, 64, tid);
    CP_COMMIT();

    const int rowA = lane & 15, hi16 = (lane >> 4) << 4;

    for (int ut = 0; ut < nU; ut++) {
        const int u0 = ut * 64;
        CP_WAIT1();                    // stage ut done; ut+1 may be in flight
        __syncthreads();
        if (ut + 2 < nU)
            load_stage(smem_base + ((ut+2)%3)*STAGE, bh, u0 + 128, tid);
        CP_COMMIT();

        const uint32_t sb  = smem_base + (ut%3)*STAGE;
        const uint32_t sQh = sb + OFF_QH, sQl = sb + OFF_QL;
        const uint32_t sEh = sb + OFF_EH, sEl = sb + OFF_EL;

        float S[8][4];
        #pragma unroll
        for (int n = 0; n < 8; n++)
            #pragma unroll
            for (int a = 0; a < 4; a++) S[n][a] = 0.f;

        // MMA1: S[t,u] = sum_i R[t,i] * Qr[u,i]  (3 bf16 products)
        #pragma unroll
        for (int jj = 0; jj < 4; jj++) {
            #pragma unroll
            for (int kk = 0; kk < 4; kk++) {
                int off = (16*jj + rowA)*128 + 32*kk + hi16;
                int sw  = SWZ(off);
                uint32_t qh[4], ql[4];
                ldm4(qh, sQh + sw);
                ldm4(ql, sQl + sw);
                hmma(S[2*jj],   Ah[kk], qh[0], qh[2]);
                hmma(S[2*jj+1], Ah[kk], qh[1], qh[3]);
                hmma(S[2*jj],   Al[kk], qh[0], qh[2]);
                hmma(S[2*jj+1], Al[kk], qh[1], qh[3]);
                hmma(S[2*jj],   Ah[kk], ql[0], ql[2]);
                hmma(S[2*jj+1], Ah[kk], ql[1], ql[3]);
            }
        }

        // causal mask in C fragments (only diagonal-straddling u-tiles)
        if (u0 + 63 > trow) {
            const int tA = trow + gid, tB = tA + 8;
            #pragma unroll
            for (int n = 0; n < 8; n++) {
                const int uA = u0 + 8*n + 2*tig, uB = uA + 1;
                if (uA > tA) S[n][0] = 0.f;
                if (uB > tA) S[n][1] = 0.f;
                if (uA > tB) S[n][2] = 0.f;
                if (uB > tB) S[n][3] = 0.f;
            }
        }

        // split S -> bf16 hi/lo A-fragments; MMA2: O[t,i] += S[t,u]*ErT[i,u]
        #pragma unroll
        for (int kk = 0; kk < 4; kk++) {
            uint32_t a2h[4], a2l[4];
            split2(S[2*kk][0],   S[2*kk][1],   a2h[0], a2l[0]);
            split2(S[2*kk][2],   S[2*kk][3],   a2h[1], a2l[1]);
            split2(S[2*kk+1][0], S[2*kk+1][1], a2h[2], a2l[2]);
            split2(S[2*kk+1][2], S[2*kk+1][3], a2h[3], a2l[3]);
            #pragma unroll
            for (int jj = 0; jj < 4; jj++) {
                int off = (16*jj + rowA)*128 + 32*kk + hi16;
                int sw  = SWZ(off);
                uint32_t eh[4], el[4];
                ldm4(eh, sEh + sw);
                ldm4(el, sEl + sw);
                hmma(O[2*jj],   a2h, eh[0], eh[2]);
                hmma(O[2*jj+1], a2h, eh[1], eh[3]);
                hmma(O[2*jj],   a2l, eh[0], eh[2]);
                hmma(O[2*jj+1], a2l, eh[1], eh[3]);
                hmma(O[2*jj],   a2h, el[0], el[2]);
                hmma(O[2*jj+1], a2h, el[1], el[3]);
            }
        }
    }

    // store per-h partial
    {
        const int tA = trow + gid;
        #pragma unroll
        for (int n = 0; n < 8; n++) {
            const int col = 8*n + 2*tig;
            *(float2*)&g_part[((size_t)bh*NT_ + tA    )*N_ + col] = make_float2(O[n][0], O[n][1]);
            *(float2*)&g_part[((size_t)bh*NT_ + tA + 8)*N_ + col] = make_float2(O[n][2], O[n][3]);
        }
    }
}

// ---------------- K3: reduce over h ----------------
__global__ __launch_bounds__(256) void k3_kernel(float* __restrict__ out) {
    const int v = blockIdx.x * 256 + threadIdx.x;
    const int b = v >> 15;
    const int r = v & 32767;
    const float4* p4 = (const float4*)g_part;
    float4 s = make_float4(0.f, 0.f, 0.f, 0.f);
    #pragma unroll
    for (int h = 0; h < NH_; h++) {
        float4 p = p4[((size_t)(b*NH_ + h) << 15) + r];
        s.x += p.x; s.y += p.y; s.z += p.z; s.w += p.w;
    }
    ((float4*)out)[v] = s;
}

extern "C" void kernel_launch(void* const* d_in, const int* in_sizes, int n_in,
                              void* d_out, int out_size) {
    const float* R = (const float*)d_in[0];
    const float* Q = (const float*)d_in[1];
    const float* E = (const float*)d_in[2];
    float* out = (float*)d_out;

    cudaFuncSetAttribute(k1_kernel, cudaFuncAttributeMaxDynamicSharedMemorySize, K1_SMEM);
    cudaFuncSetAttribute(k2_kernel, cudaFuncAttributeMaxDynamicSharedMemorySize, K2_SMEM);

    k0_kernel<<<1024, 256>>>(R);
    k1_kernel<<<dim3(16, D_, NH_), 256, K1_SMEM>>>(R, Q, E);
    k2_kernel<<<dim3(128, D_), 256, K2_SMEM>>>();
    k3_kernel<<<(D_*NT_*N_/4) / 256, 256>>>(out);
}

// round 6
// speedup vs baseline: 4.2045x; 1.4654x over previous
#include <cuda_runtime.h>
#include <cuda_fp16.h>
#include <cstdint>

#define D_  8
#define NT_ 2048
#define N_  64
#define NH_ 8

// ---------------- device scratch (allocation-free) ----------------
__device__ __align__(16) __half g_Rhi[D_*NT_*N_];
__device__ __align__(16) __half g_Rlo[D_*NT_*N_];
__device__ __align__(16) __half g_Qh [(size_t)D_*NH_*NT_*N_];  // Qr  [bh][u][i] fp16
__device__ __align__(16) __half g_EhT[(size_t)D_*NH_*N_*NT_];  // ErT [bh][i][u] fp16
__device__ __align__(16) float  g_part[(size_t)D_*NH_*NT_*N_]; // [bh][t][i]

// ---------------- helpers ----------------
__device__ __forceinline__ uint32_t smem_u32(const void* p) {
    uint32_t a;
    asm("{ .reg .u64 t; cvta.to.shared.u64 t, %1; cvt.u32.u64 %0, t; }" : "=r"(a) : "l"(p));
    return a;
}
#define SWZ(o) ((o) ^ (((o) >> 3) & 0x70))

#define CP16(s, g) asm volatile("cp.async.ca.shared.global [%0], [%1], 16;" :: "r"(s), "l"(g) : "memory")
#define CP_COMMIT() asm volatile("cp.async.commit_group;" ::: "memory")
#define CP_WAIT1()  asm volatile("cp.async.wait_group 1;" ::: "memory")
#define CP_WAIT0()  asm volatile("cp.async.wait_group 0;" ::: "memory")

__device__ __forceinline__ void ldm4(uint32_t* r, uint32_t addr) {
    asm volatile("ldmatrix.sync.aligned.m8n8.x4.shared.b16 {%0,%1,%2,%3}, [%4];"
        : "=r"(r[0]), "=r"(r[1]), "=r"(r[2]), "=r"(r[3]) : "r"(addr));
}
__device__ __forceinline__ void hmma(float* c, const uint32_t* a, uint32_t b0, uint32_t b1) {
    asm("mma.sync.aligned.m16n8k16.row.col.f32.f16.f16.f32 "
        "{%0,%1,%2,%3},{%4,%5,%6,%7},{%8,%9},{%0,%1,%2,%3};"
        : "+f"(c[0]), "+f"(c[1]), "+f"(c[2]), "+f"(c[3])
        : "r"(a[0]), "r"(a[1]), "r"(a[2]), "r"(a[3]), "r"(b0), "r"(b1));
}
__device__ __forceinline__ uint32_t pack_h2(half2 h) { return *reinterpret_cast<uint32_t*>(&h); }
__device__ __forceinline__ uint32_t f2h2(float f0, float f1) {
    half2 h = __floats2half2_rn(f0, f1);   // f0 -> low half
    return pack_h2(h);
}
// fp16 split: f = hi + lo with |f - hi - lo| ~ 2^-24 |f|
__device__ __forceinline__ void split2h(float f0, float f1, uint32_t& hi, uint32_t& lo) {
    half2 h = __floats2half2_rn(f0, f1);
    float2 hf = __half22float2(h);
    half2 l = __floats2half2_rn(f0 - hf.x, f1 - hf.y);
    hi = pack_h2(h); lo = pack_h2(l);
}

// ---------------- K0: split R into fp16 hi/lo ----------------
__global__ __launch_bounds__(256) void k0_kernel(const float* __restrict__ R) {
    const int idx = blockIdx.x * 256 + threadIdx.x;       // 262144 float4s
    float4 v = ((const float4*)R)[idx];
    uint32_t h01, l01, h23, l23;
    split2h(v.x, v.y, h01, l01);
    split2h(v.z, v.w, h23, l23);
    ((uint2*)g_Rhi)[idx] = make_uint2(h01, h23);
    ((uint2*)g_Rlo)[idx] = make_uint2(l01, l23);
}

// ---------------- K1: HMMA precompute Qr[u,i] and ErT[i,u] (fp16) ----------------
// smem: sQ 0..8K (Qh [i][j]), sEh 8K..16K, sEl 16K..24K, sRh 24K..40K ([u][j], 128 rows)
#define K1_SQ  0
#define K1_SEH 8192
#define K1_SEL 16384
#define K1_SRH 24576
#define K1_SMEM 40960

__global__ __launch_bounds__(256) void k1_kernel(const float* __restrict__ Q,
                                                 const float* __restrict__ E) {
    extern __shared__ char sm1[];
    const uint32_t sb = smem_u32(sm1);
    const int tid = threadIdx.x;
    const int b = blockIdx.y, h = blockIdx.z;
    const int u0 = blockIdx.x * 128;
    const int bh = b*NH_ + h;

    {   // stage Rh tile (128 rows x 128B) via cp.async, swizzled
        const char* rh = (const char*)g_Rhi + ((size_t)(b*NT_ + u0) * N_) * 2;
        #pragma unroll
        for (int qd = 0; qd < 4; qd++) {
            int c = tid + qd*256;                 // 0..1023 16B chunks
            int row = c >> 3, ch = (c & 7) * 16;
            CP16(sb + K1_SRH + SWZ(row*128 + ch), rh + row*128 + ch);
        }
        CP_COMMIT();
    }
    // Q/E fp32 -> fp16 (E split) into swizzled smem
    for (int p = tid; p < 64*16; p += 256) {
        int i = p >> 4, q4 = p & 15;
        float4 qv = *(const float4*)&Q[((size_t)h*N_ + i)*N_ + q4*4];
        float4 ev = *(const float4*)&E[((size_t)h*N_ + i)*N_ + q4*4];
        uint32_t off = i*128 + q4*8;
        uint32_t sw0 = SWZ(off), sw1 = SWZ(off + 4);
        *(uint32_t*)(sm1 + K1_SQ  + sw0) = f2h2(qv.x, qv.y);
        *(uint32_t*)(sm1 + K1_SQ  + sw1) = f2h2(qv.z, qv.w);
        uint32_t eh0, el0, eh1, el1;
        split2h(ev.x, ev.y, eh0, el0);
        split2h(ev.z, ev.w, eh1, el1);
        *(uint32_t*)(sm1 + K1_SEH + sw0) = eh0;
        *(uint32_t*)(sm1 + K1_SEH + sw1) = eh1;
        *(uint32_t*)(sm1 + K1_SEL + sw0) = el0;
        *(uint32_t*)(sm1 + K1_SEL + sw1) = el1;
    }
    CP_WAIT0();
    __syncthreads();

    const int w = tid >> 5, lane = tid & 31;
    const int gid = lane >> 2, tig = lane & 3;
    const int rowA = lane & 15, hi16 = (lane >> 4) << 4;

    // ---- GEMM A: Qr[u,i] = sum_j (Rh+Rl)[u,j] * Qh[i,j]   (warp w: u-tile 16w)
    {
        const int urow = u0 + 16*w;
        uint32_t Ah[4][4], Al[4][4];
        size_t r0 = ((size_t)b*NT_ + urow + gid)*N_;
        size_t r1 = r0 + 8*N_;
        #pragma unroll
        for (int kk = 0; kk < 4; kk++) {
            int c0 = 16*kk + 2*tig, c1 = c0 + 8;
            Ah[kk][0] = *(const uint32_t*)((const char*)g_Rhi + (r0 + c0)*2);
            Ah[kk][1] = *(const uint32_t*)((const char*)g_Rhi + (r1 + c0)*2);
            Ah[kk][2] = *(const uint32_t*)((const char*)g_Rhi + (r0 + c1)*2);
            Ah[kk][3] = *(const uint32_t*)((const char*)g_Rhi + (r1 + c1)*2);
            Al[kk][0] = *(const uint32_t*)((const char*)g_Rlo + (r0 + c0)*2);
            Al[kk][1] = *(const uint32_t*)((const char*)g_Rlo + (r1 + c0)*2);
            Al[kk][2] = *(const uint32_t*)((const char*)g_Rlo + (r0 + c1)*2);
            Al[kk][3] = *(const uint32_t*)((const char*)g_Rlo + (r1 + c1)*2);
        }
        float C[8][4];
        #pragma unroll
        for (int n = 0; n < 8; n++)
            #pragma unroll
            for (int a = 0; a < 4; a++) C[n][a] = 0.f;
        #pragma unroll
        for (int jj = 0; jj < 4; jj++) {
            #pragma unroll
            for (int kk = 0; kk < 4; kk++) {
                uint32_t qh[4];
                ldm4(qh, sb + K1_SQ + SWZ((16*jj + rowA)*128 + 32*kk + hi16));
                hmma(C[2*jj],   Ah[kk], qh[0], qh[2]);
                hmma(C[2*jj],   Al[kk], qh[0], qh[2]);
                hmma(C[2*jj+1], Ah[kk], qh[1], qh[3]);
                hmma(C[2*jj+1], Al[kk], qh[1], qh[3]);
            }
        }
        const int uA = urow + gid;
        #pragma unroll
        for (int n = 0; n < 8; n++) {
            int col = 8*n + 2*tig;
            *(uint32_t*)((char*)g_Qh + (((size_t)bh*NT_ + uA    )*N_ + col)*2) = f2h2(C[n][0], C[n][1]);
            *(uint32_t*)((char*)g_Qh + (((size_t)bh*NT_ + uA + 8)*N_ + col)*2) = f2h2(C[n][2], C[n][3]);
        }
    }

    // ---- GEMM B: ErT[i,u] = sum_j (Eh+El)[i,j] * Rh[u,j]
    // warp w: m-tile (w&3) of i, n-half (w>>2) of u
    {
        const int mi = (w & 3) * 16;
        const int un = (w >> 2) * 64;
        uint32_t Ah[4][4], Al[4][4];
        #pragma unroll
        for (int kk = 0; kk < 4; kk++) {
            ldm4(Ah[kk], sb + K1_SEH + SWZ((mi + rowA)*128 + 32*kk + hi16));
            ldm4(Al[kk], sb + K1_SEL + SWZ((mi + rowA)*128 + 32*kk + hi16));
        }
        float C[8][4];
        #pragma unroll
        for (int n = 0; n < 8; n++)
            #pragma unroll
            for (int a = 0; a < 4; a++) C[n][a] = 0.f;
        #pragma unroll
        for (int jj = 0; jj < 4; jj++) {
            #pragma unroll
            for (int kk = 0; kk < 4; kk++) {
                uint32_t rh[4];
                ldm4(rh, sb + K1_SRH + SWZ((un + 16*jj + rowA)*128 + 32*kk + hi16));
                hmma(C[2*jj],   Ah[kk], rh[0], rh[2]);
                hmma(C[2*jj],   Al[kk], rh[0], rh[2]);
                hmma(C[2*jj+1], Ah[kk], rh[1], rh[3]);
                hmma(C[2*jj+1], Al[kk], rh[1], rh[3]);
            }
        }
        const int iA = mi + gid;
        #pragma unroll
        for (int n = 0; n < 8; n++) {
            int col = u0 + un + 8*n + 2*tig;
            *(uint32_t*)((char*)g_EhT + (((size_t)bh*N_ + iA    )*NT_ + col)*2) = f2h2(C[n][0], C[n][1]);
            *(uint32_t*)((char*)g_EhT + (((size_t)bh*N_ + iA + 8)*NT_ + col)*2) = f2h2(C[n][2], C[n][3]);
        }
    }
}

// ---------------- K2: HMMA masked attention core (fp16 2-product) ----------------
#define OFF_QH 0
#define OFF_EH 8192
#define STAGE  16384
#define K2_SMEM (3*STAGE)

__device__ __forceinline__ void load_stage(uint32_t sbase, int bh, int u0, int tid) {
    const char* q_h = (const char*)g_Qh  + (((size_t)bh*NT_ + u0)*N_)*2;
    const char* e_h = (const char*)g_EhT + (((size_t)bh*N_)*NT_ + u0)*2;
    #pragma unroll
    for (int qd = 0; qd < 2; qd++) {
        int c   = tid + qd*256;            // 0..511 16B chunks
        int row = c >> 3, ch = (c & 7) * 16;
        int sw  = SWZ(row*128 + ch);
        CP16(sbase + OFF_QH + sw, q_h + row*128 + ch);
        CP16(sbase + OFF_EH + sw, e_h + (size_t)row*(NT_*2) + ch);
    }
}

__global__ __launch_bounds__(256, 1) void k2_kernel() {
    extern __shared__ char smem[];
    const uint32_t smem_base = smem_u32(smem);
    const int tid  = threadIdx.x;
    const int w    = tid >> 5, lane = tid & 31;
    const int gid  = lane >> 2, tig = lane & 3;
    const int b    = blockIdx.y, x = blockIdx.x;
    const int tt   = 15 - (x >> 3), h = x & 7;     // big tiles first
    const int t0   = tt * 128;
    const int bh   = b*NH_ + h;
    const int trow = t0 + 16*w;                    // this warp's m16 tile

    // R A-fragments (registers for whole block)
    uint32_t Ah[4][4], Al[4][4];
    {
        size_t r0 = ((size_t)b*NT_ + trow + gid)*N_;
        size_t r1 = r0 + 8*N_;
        #pragma unroll
        for (int kk = 0; kk < 4; kk++) {
            int c0 = 16*kk + 2*tig, c1 = c0 + 8;
            Ah[kk][0] = *(const uint32_t*)((const char*)g_Rhi + (r0 + c0)*2);
            Ah[kk][1] = *(const uint32_t*)((const char*)g_Rhi + (r1 + c0)*2);
            Ah[kk][2] = *(const uint32_t*)((const char*)g_Rhi + (r0 + c1)*2);
            Ah[kk][3] = *(const uint32_t*)((const char*)g_Rhi + (r1 + c1)*2);
            Al[kk][0] = *(const uint32_t*)((const char*)g_Rlo + (r0 + c0)*2);
            Al[kk][1] = *(const uint32_t*)((const char*)g_Rlo + (r1 + c0)*2);
            Al[kk][2] = *(const uint32_t*)((const char*)g_Rlo + (r0 + c1)*2);
            Al[kk][3] = *(const uint32_t*)((const char*)g_Rlo + (r1 + c1)*2);
        }
    }

    float O[8][4];
    #pragma unroll
    for (int n = 0; n < 8; n++)
        #pragma unroll
        for (int a = 0; a < 4; a++) O[n][a] = 0.f;

    const int nU = (tt + 1) * 2;       // >= 2
    load_stage(smem_base, bh, 0, tid);
    CP_COMMIT();
    load_stage(smem_base + STAGE, bh, 64, tid);
    CP_COMMIT();

    const int rowA = lane & 15, hi16 = (lane >> 4) << 4;

    for (int ut = 0; ut < nU; ut++) {
        const int u0 = ut * 64;
        CP_WAIT1();
        __syncthreads();
        if (ut + 2 < nU)
            load_stage(smem_base + ((ut+2)%3)*STAGE, bh, u0 + 128, tid);
        CP_COMMIT();

        if (u0 <= trow + 15) {         // skip fully-masked diagonal work (warp-uniform)
            const uint32_t sb  = smem_base + (ut%3)*STAGE;
            const uint32_t sQh = sb + OFF_QH, sEh = sb + OFF_EH;

            float S[8][4];
            #pragma unroll
            for (int n = 0; n < 8; n++)
                #pragma unroll
                for (int a = 0; a < 4; a++) S[n][a] = 0.f;

            // MMA1: S[t,u] = sum_i (Rh+Rl)[t,i] * Qrh[u,i]
            #pragma unroll
            for (int jj = 0; jj < 4; jj++) {
                #pragma unroll
                for (int kk = 0; kk < 4; kk++) {
                    uint32_t qh[4];
                    ldm4(qh, sQh + SWZ((16*jj + rowA)*128 + 32*kk + hi16));
                    hmma(S[2*jj],   Ah[kk], qh[0], qh[2]);
                    hmma(S[2*jj],   Al[kk], qh[0], qh[2]);
                    hmma(S[2*jj+1], Ah[kk], qh[1], qh[3]);
                    hmma(S[2*jj+1], Al[kk], qh[1], qh[3]);
                }
            }

            // causal mask (diagonal-straddling tiles only)
            if (u0 + 63 > trow) {
                const int tA = trow + gid, tB = tA + 8;
                #pragma unroll
                for (int n = 0; n < 8; n++) {
                    const int uA = u0 + 8*n + 2*tig, uB = uA + 1;
                    if (uA > tA) S[n][0] = 0.f;
                    if (uB > tA) S[n][1] = 0.f;
                    if (uA > tB) S[n][2] = 0.f;
                    if (uB > tB) S[n][3] = 0.f;
                }
            }

            // split S -> fp16 hi/lo; MMA2: O[t,i] += (Sh+Sl)[t,u] * ErTh[i,u]
            #pragma unroll
            for (int kk = 0; kk < 4; kk++) {
                uint32_t a2h[4], a2l[4];
                split2h(S[2*kk][0],   S[2*kk][1],   a2h[0], a2l[0]);
                split2h(S[2*kk][2],   S[2*kk][3],   a2h[1], a2l[1]);
                split2h(S[2*kk+1][0], S[2*kk+1][1], a2h[2], a2l[2]);
                split2h(S[2*kk+1][2], S[2*kk+1][3], a2h[3], a2l[3]);
                #pragma unroll
                for (int jj = 0; jj < 4; jj++) {
                    uint32_t eh[4];
                    ldm4(eh, sEh + SWZ((16*jj + rowA)*128 + 32*kk + hi16));
                    hmma(O[2*jj],   a2h, eh[0], eh[2]);
                    hmma(O[2*jj],   a2l, eh[0], eh[2]);
                    hmma(O[2*jj+1], a2h, eh[1], eh[3]);
                    hmma(O[2*jj+1], a2l, eh[1], eh[3]);
                }
            }
        }
    }

    // store per-h partial
    {
        const int tA = trow + gid;
        #pragma unroll
        for (int n = 0; n < 8; n++) {
            const int col = 8*n + 2*tig;
            *(float2*)&g_part[((size_t)bh*NT_ + tA    )*N_ + col] = make_float2(O[n][0], O[n][1]);
            *(float2*)&g_part[((size_t)bh*NT_ + tA + 8)*N_ + col] = make_float2(O[n][2], O[n][3]);
        }
    }
}

// ---------------- K3: reduce over h ----------------
__global__ __launch_bounds__(256) void k3_kernel(float* __restrict__ out) {
    const int v = blockIdx.x * 256 + threadIdx.x;
    const int b = v >> 15;
    const int r = v & 32767;
    const float4* p4 = (const float4*)g_part;
    float4 s = make_float4(0.f, 0.f, 0.f, 0.f);
    #pragma unroll
    for (int h = 0; h < NH_; h++) {
        float4 p = p4[((size_t)(b*NH_ + h) << 15) + r];
        s.x += p.x; s.y += p.y; s.z += p.z; s.w += p.w;
    }
    ((float4*)out)[v] = s;
}

extern "C" void kernel_launch(void* const* d_in, const int* in_sizes, int n_in,
                              void* d_out, int out_size) {
    const float* R = (const float*)d_in[0];
    const float* Q = (const float*)d_in[1];
    const float* E = (const float*)d_in[2];
    float* out = (float*)d_out;

    cudaFuncSetAttribute(k1_kernel, cudaFuncAttributeMaxDynamicSharedMemorySize, K1_SMEM);
    cudaFuncSetAttribute(k2_kernel, cudaFuncAttributeMaxDynamicSharedMemorySize, K2_SMEM);

    k0_kernel<<<1024, 256>>>(R);
    k1_kernel<<<dim3(16, D_, NH_), 256, K1_SMEM>>>(Q, E);
    k2_kernel<<<dim3(128, D_), 256, K2_SMEM>>>();
    k3_kernel<<<(D_*NT_*N_/4) / 256, 256>>>(out);
}